// round 2
// baseline (speedup 1.0000x reference)
#include <cuda_runtime.h>
#include <cuda_bf16.h>
#include <cstdint>

// Problem constants
#define B_  64
#define L_  1024
#define H_  128

// ---------------------------------------------------------------------------
// Scratch (allocation-free rule: __device__ globals)
// ---------------------------------------------------------------------------
__device__ __align__(16) __nv_bfloat16 g_Ahi[(size_t)B_*L_*H_]; // (body*w3) hi
__device__ __align__(16) __nv_bfloat16 g_Alo[(size_t)B_*L_*H_]; // (body*w3) lo
__device__ __align__(16) __nv_bfloat16 g_Phi[(size_t)B_*L_*H_]; // pun hi
__device__ __align__(16) __nv_bfloat16 g_Plo[(size_t)B_*L_*H_]; // pun lo
__device__ float g_sbody[B_*L_];
__device__ float g_spun [B_*L_];

// ---------------------------------------------------------------------------
// Helpers (base-arch only: NO tcgen05 — ptxas target is sm_103, not sm_103a)
// ---------------------------------------------------------------------------
__device__ __forceinline__ uint32_t smem_u32(const void* p) {
    uint32_t a;
    asm("{ .reg .u64 t; cvta.to.shared.u64 t, %1; cvt.u32.u64 %0, t; }" : "=r"(a) : "l"(p));
    return a;
}

__device__ __forceinline__ void ldsm_x4(uint32_t* r, uint32_t addr) {
    asm volatile("ldmatrix.sync.aligned.m8n8.x4.shared.b16 {%0,%1,%2,%3}, [%4];"
        : "=r"(r[0]), "=r"(r[1]), "=r"(r[2]), "=r"(r[3]) : "r"(addr));
}
__device__ __forceinline__ void ldsm_x2(uint32_t* r, uint32_t addr) {
    asm volatile("ldmatrix.sync.aligned.m8n8.x2.shared.b16 {%0,%1}, [%2];"
        : "=r"(r[0]), "=r"(r[1]) : "r"(addr));
}

// D += A * B  (m16n8k16, bf16 in, f32 accum)
__device__ __forceinline__ void mma_bf16(float* d, const uint32_t* a, const uint32_t* b) {
    asm volatile(
        "mma.sync.aligned.m16n8k16.row.col.f32.bf16.bf16.f32 "
        "{%0,%1,%2,%3}, {%4,%5,%6,%7}, {%8,%9}, {%0,%1,%2,%3};"
        : "+f"(d[0]), "+f"(d[1]), "+f"(d[2]), "+f"(d[3])
        : "r"(a[0]), "r"(a[1]), "r"(a[2]), "r"(a[3]), "r"(b[0]), "r"(b[1]));
}

// ---------------------------------------------------------------------------
// Kernel 1: preprocess — split body*w3 and pun into bf16 hi/lo, rank-1 vectors
// ---------------------------------------------------------------------------
__global__ void __launch_bounds__(128) prep_kernel(const float* __restrict__ body,
                                                   const float* __restrict__ pun,
                                                   const float* __restrict__ w_u) {
    const int r = blockIdx.x;          // 0 .. B_*L_-1 (global row)
    const int d = threadIdx.x;         // 0 .. 127
    const int wid = d >> 5, lane = d & 31;

    const float w1 = w_u[d];
    const float w2 = w_u[H_ + d];
    const float w3 = w_u[2 * H_ + d];

    const size_t idx = (size_t)r * H_ + d;
    const float bv = body[idx];
    const float pv = pun[idx];

    const float a = bv * w3;
    const __nv_bfloat16 ah = __float2bfloat16(a);
    const __nv_bfloat16 al = __float2bfloat16(a - __bfloat162float(ah));
    g_Ahi[idx] = ah; g_Alo[idx] = al;

    const __nv_bfloat16 ph = __float2bfloat16(pv);
    const __nv_bfloat16 pl = __float2bfloat16(pv - __bfloat162float(ph));
    g_Phi[idx] = ph; g_Plo[idx] = pl;

    // block-reduce dot products
    float sb = bv * w1;
    float sp = pv * w2;
    #pragma unroll
    for (int o = 16; o > 0; o >>= 1) {
        sb += __shfl_down_sync(0xFFFFFFFFu, sb, o);
        sp += __shfl_down_sync(0xFFFFFFFFu, sp, o);
    }
    __shared__ float pb[4], pq[4];
    if (lane == 0) { pb[wid] = sb; pq[wid] = sp; }
    __syncthreads();
    if (d == 0) {
        g_sbody[r] = pb[0] + pb[1] + pb[2] + pb[3];
        g_spun[r]  = pq[0] + pq[1] + pq[2] + pq[3];
    }
}

// ---------------------------------------------------------------------------
// Kernel 2: mma.sync bf16 split-3 batched GEMM, CTA tile 128x128, K-chunk 64
// ---------------------------------------------------------------------------
static constexpr int KC = 64;
static constexpr int OFF_SB  = 0;      // 128 f32 (sbody slice)
static constexpr int OFF_SP  = 512;    // 128 f32 (spun slice)
static constexpr int OFF_A_HI = 1024;               // 128 x 64 bf16 = 16 KB
static constexpr int OFF_A_LO = OFF_A_HI + 16384;
static constexpr int OFF_P_HI = OFF_A_LO + 16384;
static constexpr int OFF_P_LO = OFF_P_HI + 16384;
static constexpr int SMEM_TOTAL = OFF_P_LO + 16384; // 66560 B -> occupancy 2-3

// Load a 128x64 bf16 slab into smem with per-8-row chunk-XOR swizzle.
// Each row = 8 chunks of 16B; phys_chunk = chunk ^ (row & 7).
__device__ __forceinline__ void load_tile_kc(char* dst, const __nv_bfloat16* __restrict__ g,
                                             int row0, int kk, int tid) {
    #pragma unroll
    for (int l = 0; l < 4; l++) {
        const int cidx = tid + l * 256;       // 0..1023 chunk index
        const int row  = cidx >> 3;
        const int ch   = cidx & 7;
        const uint4 v = *reinterpret_cast<const uint4*>(
            g + (size_t)(row0 + row) * H_ + kk + ch * 8);
        *reinterpret_cast<uint4*>(dst + row * 128 + ((ch ^ (row & 7)) << 4)) = v;
    }
}

__global__ void __launch_bounds__(256, 2)
gemm_kernel(float* __restrict__ out) {
    extern __shared__ char smem[];
    const int tid  = threadIdx.x;
    const int lane = tid & 31;
    const int warp = tid >> 5;
    const int wm = warp & 1;        // 0..1 -> 64 rows
    const int wn = warp >> 1;       // 0..3 -> 32 cols
    const int m_base = wm * 64, n_base = wn * 32;

    const int b  = blockIdx.z;
    const int i0 = blockIdx.y * 128;
    const int j0 = blockIdx.x * 128;
    const size_t base = (size_t)b * L_ * H_;

    // rank-1 vector slices
    if (tid < 128)       ((float*)(smem + OFF_SB))[tid]       = g_sbody[b * L_ + i0 + tid];
    else                 ((float*)(smem + OFF_SP))[tid - 128] = g_spun [b * L_ + j0 + (tid - 128)];

    float acc[4][4][4];
    #pragma unroll
    for (int mi = 0; mi < 4; mi++)
        #pragma unroll
        for (int ni = 0; ni < 4; ni++)
            #pragma unroll
            for (int k = 0; k < 4; k++) acc[mi][ni][k] = 0.f;

    const uint32_t sbase = smem_u32(smem);

    #pragma unroll
    for (int kk = 0; kk < H_; kk += KC) {
        if (kk) __syncthreads();   // previous chunk's compute done before overwrite
        load_tile_kc(smem + OFF_A_HI, g_Ahi + base, i0, kk, tid);
        load_tile_kc(smem + OFF_A_LO, g_Alo + base, i0, kk, tid);
        load_tile_kc(smem + OFF_P_HI, g_Phi + base, j0, kk, tid);
        load_tile_kc(smem + OFF_P_LO, g_Plo + base, j0, kk, tid);
        __syncthreads();

        #pragma unroll
        for (int ks = 0; ks < KC / 16; ks++) {
            // --- B fragments (P tiles), n8k16, ldmatrix.x2 non-transposed ---
            uint32_t bHi[4][2], bLo[4][2];
            {
                const int l16    = lane & 15;
                const int nr_off = l16 & 7;
                const int bk     = ks * 16 + (l16 >> 3) * 8;
                const int chunk  = bk >> 3;
                #pragma unroll
                for (int ni = 0; ni < 4; ni++) {
                    const int nrow = n_base + ni * 8 + nr_off;
                    const uint32_t off = (uint32_t)(nrow * 128 + ((chunk ^ (nrow & 7)) << 4));
                    ldsm_x2(bHi[ni], sbase + OFF_P_HI + off);
                    ldsm_x2(bLo[ni], sbase + OFF_P_LO + off);
                }
            }
            // --- A fragments + MMAs ---
            const int quad   = lane >> 3;
            const int ar_off = (lane & 7) + (quad & 1) * 8;
            const int ak     = ks * 16 + (quad >> 1) * 8;
            const int achunk = ak >> 3;
            #pragma unroll
            for (int mi = 0; mi < 4; mi++) {
                uint32_t aHi[4], aLo[4];
                const int arow = m_base + mi * 16 + ar_off;
                const uint32_t off = (uint32_t)(arow * 128 + ((achunk ^ (arow & 7)) << 4));
                ldsm_x4(aHi, sbase + OFF_A_HI + off);
                ldsm_x4(aLo, sbase + OFF_A_LO + off);
                #pragma unroll
                for (int ni = 0; ni < 4; ni++) {
                    mma_bf16(acc[mi][ni], aHi, bHi[ni]);  // hi*hi
                    mma_bf16(acc[mi][ni], aHi, bLo[ni]);  // hi*lo
                    mma_bf16(acc[mi][ni], aLo, bHi[ni]);  // lo*hi
                }
            }
        }
    }

    // --- epilogue: acc + sbody[row] + spun[col] -> gmem (float2 stores) ---
    const float* sbV = (const float*)(smem + OFF_SB);
    const float* spV = (const float*)(smem + OFF_SP);
    const int r4 = lane >> 2;
    const int c2 = (lane & 3) << 1;
    float* outB = out + (size_t)b * L_ * L_;

    #pragma unroll
    for (int mi = 0; mi < 4; mi++) {
        const float sb0 = sbV[m_base + mi * 16 + r4];
        const float sb1 = sbV[m_base + mi * 16 + 8 + r4];
        const int row0 = i0 + m_base + mi * 16 + r4;
        #pragma unroll
        for (int ni = 0; ni < 4; ni++) {
            const int col = j0 + n_base + ni * 8 + c2;
            const float sp0 = spV[n_base + ni * 8 + c2];
            const float sp1 = spV[n_base + ni * 8 + c2 + 1];
            float2 v0 = make_float2(acc[mi][ni][0] + sb0 + sp0,
                                    acc[mi][ni][1] + sb0 + sp1);
            float2 v1 = make_float2(acc[mi][ni][2] + sb1 + sp0,
                                    acc[mi][ni][3] + sb1 + sp1);
            *reinterpret_cast<float2*>(outB + (size_t)row0 * L_ + col)       = v0;
            *reinterpret_cast<float2*>(outB + (size_t)(row0 + 8) * L_ + col) = v1;
        }
    }
}

// ---------------------------------------------------------------------------
// Launch
// ---------------------------------------------------------------------------
extern "C" void kernel_launch(void* const* d_in, const int* in_sizes, int n_in,
                              void* d_out, int out_size) {
    // metadata order: [batch_size?], body, pun, w_u — take the last three
    const float* body = (const float*)d_in[n_in - 3];
    const float* pun  = (const float*)d_in[n_in - 2];
    const float* w_u  = (const float*)d_in[n_in - 1];
    float* out = (float*)d_out;

    prep_kernel<<<B_ * L_, 128>>>(body, pun, w_u);

    static bool attr_set = false;
    if (!attr_set) {
        cudaFuncSetAttribute(gemm_kernel, cudaFuncAttributeMaxDynamicSharedMemorySize, SMEM_TOTAL);
        attr_set = true;
    }
    gemm_kernel<<<dim3(8, 8, B_), 256, SMEM_TOTAL>>>(out);
}

// round 3
// speedup vs baseline: 1.2454x; 1.2454x over previous
#include <cuda_runtime.h>
#include <cuda_bf16.h>
#include <cstdint>

// Problem constants
#define B_  64
#define L_  1024
#define H_  128

// ---------------------------------------------------------------------------
// Scratch (allocation-free rule: __device__ globals)
// ---------------------------------------------------------------------------
__device__ __align__(16) __nv_bfloat16 g_Ahi[(size_t)B_*L_*H_]; // (body*w3) hi
__device__ __align__(16) __nv_bfloat16 g_Alo[(size_t)B_*L_*H_]; // (body*w3) lo
__device__ __align__(16) __nv_bfloat16 g_Phi[(size_t)B_*L_*H_]; // pun hi
__device__ __align__(16) __nv_bfloat16 g_Plo[(size_t)B_*L_*H_]; // pun lo
__device__ float g_sbody[B_*L_];
__device__ float g_spun [B_*L_];

// ---------------------------------------------------------------------------
// Helpers (base-arch only: NO tcgen05 — ptxas target is sm_103, not sm_103a)
// ---------------------------------------------------------------------------
__device__ __forceinline__ uint32_t smem_u32(const void* p) {
    uint32_t a;
    asm("{ .reg .u64 t; cvta.to.shared.u64 t, %1; cvt.u32.u64 %0, t; }" : "=r"(a) : "l"(p));
    return a;
}

__device__ __forceinline__ void ldsm_x4(uint32_t* r, uint32_t addr) {
    asm volatile("ldmatrix.sync.aligned.m8n8.x4.shared.b16 {%0,%1,%2,%3}, [%4];"
        : "=r"(r[0]), "=r"(r[1]), "=r"(r[2]), "=r"(r[3]) : "r"(addr));
}

// D += A * B  (m16n8k16, bf16 in, f32 accum)
__device__ __forceinline__ void mma_bf16(float* d, const uint32_t* a, const uint32_t* b) {
    asm volatile(
        "mma.sync.aligned.m16n8k16.row.col.f32.bf16.bf16.f32 "
        "{%0,%1,%2,%3}, {%4,%5,%6,%7}, {%8,%9}, {%0,%1,%2,%3};"
        : "+f"(d[0]), "+f"(d[1]), "+f"(d[2]), "+f"(d[3])
        : "r"(a[0]), "r"(a[1]), "r"(a[2]), "r"(a[3]), "r"(b[0]), "r"(b[1]));
}

__device__ __forceinline__ void cp_async16(uint32_t dst, const void* src) {
    asm volatile("cp.async.cg.shared.global [%0], [%1], 16;" :: "r"(dst), "l"(src));
}
#define CP_COMMIT() asm volatile("cp.async.commit_group;" ::: "memory")
#define CP_WAIT(n)  asm volatile("cp.async.wait_group %0;" :: "n"(n) : "memory")

// ---------------------------------------------------------------------------
// Kernel 1: preprocess — split body*w3 and pun into bf16 hi/lo, rank-1 vectors
// One warp per row; lane handles 4 consecutive d via float4.
// ---------------------------------------------------------------------------
__device__ __forceinline__ uint32_t pack_bf2(float x, float y) {
    __nv_bfloat162 v(__float2bfloat16(x), __float2bfloat16(y));
    return *reinterpret_cast<uint32_t*>(&v);
}

__global__ void __launch_bounds__(256) prep_kernel(const float* __restrict__ body,
                                                   const float* __restrict__ pun,
                                                   const float* __restrict__ w_u) {
    const int warp = threadIdx.x >> 5, lane = threadIdx.x & 31;
    const int r = blockIdx.x * 8 + warp;           // row 0..B_*L_-1
    const int d4 = lane * 4;

    const float4 w1 = *reinterpret_cast<const float4*>(w_u + d4);
    const float4 w2 = *reinterpret_cast<const float4*>(w_u + H_ + d4);
    const float4 w3 = *reinterpret_cast<const float4*>(w_u + 2 * H_ + d4);

    const size_t idx = (size_t)r * H_ + d4;
    const float4 bv = *reinterpret_cast<const float4*>(body + idx);
    const float4 pv = *reinterpret_cast<const float4*>(pun + idx);

    // A = body*w3, split hi/lo
    float a0 = bv.x * w3.x, a1 = bv.y * w3.y, a2 = bv.z * w3.z, a3 = bv.w * w3.w;
    float h0 = __bfloat162float(__float2bfloat16(a0));
    float h1 = __bfloat162float(__float2bfloat16(a1));
    float h2 = __bfloat162float(__float2bfloat16(a2));
    float h3 = __bfloat162float(__float2bfloat16(a3));
    uint2 ahi = make_uint2(pack_bf2(a0, a1), pack_bf2(a2, a3));
    uint2 alo = make_uint2(pack_bf2(a0 - h0, a1 - h1), pack_bf2(a2 - h2, a3 - h3));
    *reinterpret_cast<uint2*>(g_Ahi + idx) = ahi;
    *reinterpret_cast<uint2*>(g_Alo + idx) = alo;

    // P = pun, split hi/lo
    float q0 = __bfloat162float(__float2bfloat16(pv.x));
    float q1 = __bfloat162float(__float2bfloat16(pv.y));
    float q2 = __bfloat162float(__float2bfloat16(pv.z));
    float q3 = __bfloat162float(__float2bfloat16(pv.w));
    uint2 phi = make_uint2(pack_bf2(pv.x, pv.y), pack_bf2(pv.z, pv.w));
    uint2 plo = make_uint2(pack_bf2(pv.x - q0, pv.y - q1), pack_bf2(pv.z - q2, pv.w - q3));
    *reinterpret_cast<uint2*>(g_Phi + idx) = phi;
    *reinterpret_cast<uint2*>(g_Plo + idx) = plo;

    // rank-1 dot products
    float sb = bv.x * w1.x + bv.y * w1.y + bv.z * w1.z + bv.w * w1.w;
    float sp = pv.x * w2.x + pv.y * w2.y + pv.z * w2.z + pv.w * w2.w;
    #pragma unroll
    for (int o = 16; o > 0; o >>= 1) {
        sb += __shfl_down_sync(0xFFFFFFFFu, sb, o);
        sp += __shfl_down_sync(0xFFFFFFFFu, sp, o);
    }
    if (lane == 0) { g_sbody[r] = sb; g_spun[r] = sp; }
}

// ---------------------------------------------------------------------------
// Kernel 2: mma.sync bf16 split-3 batched GEMM
//   CTA tile 128x128, KC=32 chunks, cp.async double-buffered.
// smem: [0]=sbody(512B) [512]=spun(512B) [1024]=buf0(32KB) [1024+32K]=buf1(32KB)
//   buffer layout: Ahi(8K) Alo(8K) Phi(8K) Plo(8K); slab = 128 rows x 64B,
//   swizzle: phys_chunk16 = ch ^ ((row>>1)&3)  (conflict-free for ldmatrix)
// ---------------------------------------------------------------------------
static constexpr int KC = 32;
static constexpr int OFF_SB  = 0;
static constexpr int OFF_SP  = 512;
static constexpr int OFF_BUF = 1024;
static constexpr int SLAB    = 8192;      // one 128x32 bf16 slab
static constexpr int BUFSZ   = 4 * SLAB;  // 32 KB
static constexpr int SMEM_TOTAL = OFF_BUF + 2 * BUFSZ; // 66560 B

__device__ __forceinline__ void load_slab(uint32_t dst, const __nv_bfloat16* __restrict__ g,
                                          int row0, int kk, int tid) {
    #pragma unroll
    for (int l = 0; l < 2; l++) {
        const int cidx = tid + l * 256;     // 0..511
        const int row  = cidx >> 2;
        const int ch   = cidx & 3;
        const uint32_t off = (uint32_t)(row * 64 + ((ch ^ ((row >> 1) & 3)) << 4));
        cp_async16(dst + off, g + (size_t)(row0 + row) * H_ + kk + ch * 8);
    }
}

__global__ void __launch_bounds__(256, 2)
gemm_kernel(float* __restrict__ out) {
    extern __shared__ char smem[];
    const uint32_t sbase = smem_u32(smem);
    const int tid  = threadIdx.x;
    const int lane = tid & 31;
    const int warp = tid >> 5;
    const int m_base = (warp & 1) * 64;   // 2 warps over M
    const int n_base = (warp >> 1) * 32;  // 4 warps over N

    const int b  = blockIdx.z;
    const int i0 = blockIdx.y * 128;
    const int j0 = blockIdx.x * 128;
    const size_t base = (size_t)b * L_ * H_;

    // rank-1 vector slices
    if (tid < 128)       ((float*)(smem + OFF_SB))[tid]       = g_sbody[b * L_ + i0 + tid];
    else                 ((float*)(smem + OFF_SP))[tid - 128] = g_spun [b * L_ + j0 + (tid - 128)];

    float acc[4][4][4];
    #pragma unroll
    for (int mi = 0; mi < 4; mi++)
        #pragma unroll
        for (int ni = 0; ni < 4; ni++)
            #pragma unroll
            for (int k = 0; k < 4; k++) acc[mi][ni][k] = 0.f;

    // fragment addressing (constant per thread)
    const int a_row  = (lane & 7) + ((lane >> 3) & 1) * 8;   // row within 16
    const int a_half = lane >> 4;                            // k half (0/1)
    const int b_row  = (lane & 7) + (lane >> 4) * 8;         // n row within 16
    const int b_half = (lane >> 3) & 1;                      // k half (0/1)

    // prologue: chunk 0
    {
        uint32_t buf = sbase + OFF_BUF;
        load_slab(buf,            g_Ahi + base, i0, 0, tid);
        load_slab(buf + SLAB,     g_Alo + base, i0, 0, tid);
        load_slab(buf + 2 * SLAB, g_Phi + base, j0, 0, tid);
        load_slab(buf + 3 * SLAB, g_Plo + base, j0, 0, tid);
        CP_COMMIT();
    }

    #pragma unroll
    for (int c = 0; c < 4; c++) {
        if (c < 3) {
            uint32_t buf = sbase + OFF_BUF + ((c + 1) & 1) * BUFSZ;
            const int kk = (c + 1) * KC;
            load_slab(buf,            g_Ahi + base, i0, kk, tid);
            load_slab(buf + SLAB,     g_Alo + base, i0, kk, tid);
            load_slab(buf + 2 * SLAB, g_Phi + base, j0, kk, tid);
            load_slab(buf + 3 * SLAB, g_Plo + base, j0, kk, tid);
            CP_COMMIT();
            CP_WAIT(1);
        } else {
            CP_WAIT(0);
        }
        __syncthreads();

        const uint32_t buf = sbase + OFF_BUF + (c & 1) * BUFSZ;
        #pragma unroll
        for (int ks = 0; ks < KC / 16; ks++) {
            // --- B fragments via ldmatrix.x4: 2 n-tiles per load ---
            uint32_t bHi[4][2], bLo[4][2];
            {
                const int chunk = ks * 2 + b_half;
                #pragma unroll
                for (int np = 0; np < 2; np++) {
                    const int nrow = n_base + np * 16 + b_row;
                    const uint32_t off = (uint32_t)(nrow * 64 + ((chunk ^ ((nrow >> 1) & 3)) << 4));
                    uint32_t r[4];
                    ldsm_x4(r, buf + 2 * SLAB + off);
                    bHi[np*2][0] = r[0]; bHi[np*2][1] = r[1];
                    bHi[np*2+1][0] = r[2]; bHi[np*2+1][1] = r[3];
                    ldsm_x4(r, buf + 3 * SLAB + off);
                    bLo[np*2][0] = r[0]; bLo[np*2][1] = r[1];
                    bLo[np*2+1][0] = r[2]; bLo[np*2+1][1] = r[3];
                }
            }
            // --- A fragments + MMAs ---
            const int achunk = ks * 2 + a_half;
            #pragma unroll
            for (int mi = 0; mi < 4; mi++) {
                uint32_t aHi[4], aLo[4];
                const int arow = m_base + mi * 16 + a_row;
                const uint32_t off = (uint32_t)(arow * 64 + ((achunk ^ ((arow >> 1) & 3)) << 4));
                ldsm_x4(aHi, buf + off);
                ldsm_x4(aLo, buf + SLAB + off);
                #pragma unroll
                for (int ni = 0; ni < 4; ni++) {
                    mma_bf16(acc[mi][ni], aHi, bHi[ni]);  // hi*hi
                    mma_bf16(acc[mi][ni], aHi, bLo[ni]);  // hi*lo
                    mma_bf16(acc[mi][ni], aLo, bHi[ni]);  // lo*hi
                }
            }
        }
        __syncthreads();
    }

    // --- epilogue: acc + sbody[row] + spun[col] -> gmem (float2 stores) ---
    const float* sbV = (const float*)(smem + OFF_SB);
    const float* spV = (const float*)(smem + OFF_SP);
    const int r4 = lane >> 2;
    const int c2 = (lane & 3) << 1;
    float* outB = out + (size_t)b * L_ * L_;

    #pragma unroll
    for (int mi = 0; mi < 4; mi++) {
        const float sb0 = sbV[m_base + mi * 16 + r4];
        const float sb1 = sbV[m_base + mi * 16 + 8 + r4];
        const int row0 = i0 + m_base + mi * 16 + r4;
        #pragma unroll
        for (int ni = 0; ni < 4; ni++) {
            const int col = j0 + n_base + ni * 8 + c2;
            const float sp0 = spV[n_base + ni * 8 + c2];
            const float sp1 = spV[n_base + ni * 8 + c2 + 1];
            float2 v0 = make_float2(acc[mi][ni][0] + sb0 + sp0,
                                    acc[mi][ni][1] + sb0 + sp1);
            float2 v1 = make_float2(acc[mi][ni][2] + sb1 + sp0,
                                    acc[mi][ni][3] + sb1 + sp1);
            *reinterpret_cast<float2*>(outB + (size_t)row0 * L_ + col)       = v0;
            *reinterpret_cast<float2*>(outB + (size_t)(row0 + 8) * L_ + col) = v1;
        }
    }
}

// ---------------------------------------------------------------------------
// Launch
// ---------------------------------------------------------------------------
extern "C" void kernel_launch(void* const* d_in, const int* in_sizes, int n_in,
                              void* d_out, int out_size) {
    // metadata order: [batch_size?], body, pun, w_u — take the last three
    const float* body = (const float*)d_in[n_in - 3];
    const float* pun  = (const float*)d_in[n_in - 2];
    const float* w_u  = (const float*)d_in[n_in - 1];
    float* out = (float*)d_out;

    prep_kernel<<<(B_ * L_) / 8, 256>>>(body, pun, w_u);

    static bool attr_set = false;
    if (!attr_set) {
        cudaFuncSetAttribute(gemm_kernel, cudaFuncAttributeMaxDynamicSharedMemorySize, SMEM_TOTAL);
        attr_set = true;
    }
    gemm_kernel<<<dim3(8, 8, B_), 256, SMEM_TOTAL>>>(out);
}

// round 4
// speedup vs baseline: 1.5469x; 1.2421x over previous
#include <cuda_runtime.h>
#include <cuda_fp16.h>
#include <cstdint>

// Problem constants
#define B_  64
#define L_  1024
#define H_  128

// ---------------------------------------------------------------------------
// Scratch (allocation-free rule: __device__ globals)
// fp16 2-term scheme: a = body*w3 -> ah (fp16); p = pun -> ph + pl (fp16 pair)
// s_cross ≈ ah·ph + ah·pl   (dropped al·p ~ 2^-11 relative)
// ---------------------------------------------------------------------------
__device__ __align__(16) __half g_Ah[(size_t)B_*L_*H_];
__device__ __align__(16) __half g_Ph[(size_t)B_*L_*H_];
__device__ __align__(16) __half g_Pl[(size_t)B_*L_*H_];
__device__ float g_sbody[B_*L_];
__device__ float g_spun [B_*L_];

// ---------------------------------------------------------------------------
// Helpers (base-arch only: NO tcgen05 — ptxas target is sm_103, not sm_103a)
// ---------------------------------------------------------------------------
__device__ __forceinline__ uint32_t smem_u32(const void* p) {
    uint32_t a;
    asm("{ .reg .u64 t; cvta.to.shared.u64 t, %1; cvt.u32.u64 %0, t; }" : "=r"(a) : "l"(p));
    return a;
}

__device__ __forceinline__ void ldsm_x4(uint32_t* r, uint32_t addr) {
    asm volatile("ldmatrix.sync.aligned.m8n8.x4.shared.b16 {%0,%1,%2,%3}, [%4];"
        : "=r"(r[0]), "=r"(r[1]), "=r"(r[2]), "=r"(r[3]) : "r"(addr));
}

// D += A * B  (m16n8k16, fp16 in, f32 accum)
__device__ __forceinline__ void mma_f16(float* d, const uint32_t* a, const uint32_t* b) {
    asm volatile(
        "mma.sync.aligned.m16n8k16.row.col.f32.f16.f16.f32 "
        "{%0,%1,%2,%3}, {%4,%5,%6,%7}, {%8,%9}, {%0,%1,%2,%3};"
        : "+f"(d[0]), "+f"(d[1]), "+f"(d[2]), "+f"(d[3])
        : "r"(a[0]), "r"(a[1]), "r"(a[2]), "r"(a[3]), "r"(b[0]), "r"(b[1]));
}

__device__ __forceinline__ void cp_async16(uint32_t dst, const void* src) {
    asm volatile("cp.async.cg.shared.global [%0], [%1], 16;" :: "r"(dst), "l"(src));
}
#define CP_COMMIT() asm volatile("cp.async.commit_group;" ::: "memory")
#define CP_WAIT(n)  asm volatile("cp.async.wait_group %0;" :: "n"(n) : "memory")

// ---------------------------------------------------------------------------
// Kernel 1: preprocess — ah = fp16(body*w3); ph/pl = fp16 split of pun;
//           rank-1 dot products. One warp per row (float4 per lane).
// ---------------------------------------------------------------------------
__device__ __forceinline__ uint32_t pack_h2(float x, float y) {
    __half2 v(__float2half(x), __float2half(y));
    return *reinterpret_cast<uint32_t*>(&v);
}

__global__ void __launch_bounds__(256) prep_kernel(const float* __restrict__ body,
                                                   const float* __restrict__ pun,
                                                   const float* __restrict__ w_u) {
    const int warp = threadIdx.x >> 5, lane = threadIdx.x & 31;
    const int r = blockIdx.x * 8 + warp;
    const int d4 = lane * 4;

    const float4 w1 = *reinterpret_cast<const float4*>(w_u + d4);
    const float4 w2 = *reinterpret_cast<const float4*>(w_u + H_ + d4);
    const float4 w3 = *reinterpret_cast<const float4*>(w_u + 2 * H_ + d4);

    const size_t idx = (size_t)r * H_ + d4;
    const float4 bv = *reinterpret_cast<const float4*>(body + idx);
    const float4 pv = *reinterpret_cast<const float4*>(pun + idx);

    // A = body*w3 -> fp16 (single term)
    float a0 = bv.x * w3.x, a1 = bv.y * w3.y, a2 = bv.z * w3.z, a3 = bv.w * w3.w;
    *reinterpret_cast<uint2*>(g_Ah + idx) =
        make_uint2(pack_h2(a0, a1), pack_h2(a2, a3));

    // P = pun -> fp16 hi/lo split
    float q0 = __half2float(__float2half(pv.x));
    float q1 = __half2float(__float2half(pv.y));
    float q2 = __half2float(__float2half(pv.z));
    float q3 = __half2float(__float2half(pv.w));
    *reinterpret_cast<uint2*>(g_Ph + idx) =
        make_uint2(pack_h2(pv.x, pv.y), pack_h2(pv.z, pv.w));
    *reinterpret_cast<uint2*>(g_Pl + idx) =
        make_uint2(pack_h2(pv.x - q0, pv.y - q1), pack_h2(pv.z - q2, pv.w - q3));

    // rank-1 dot products
    float sb = bv.x * w1.x + bv.y * w1.y + bv.z * w1.z + bv.w * w1.w;
    float sp = pv.x * w2.x + pv.y * w2.y + pv.z * w2.z + pv.w * w2.w;
    #pragma unroll
    for (int o = 16; o > 0; o >>= 1) {
        sb += __shfl_down_sync(0xFFFFFFFFu, sb, o);
        sp += __shfl_down_sync(0xFFFFFFFFu, sp, o);
    }
    if (lane == 0) { g_sbody[r] = sb; g_spun[r] = sp; }
}

// ---------------------------------------------------------------------------
// Kernel 2: mma.sync fp16 2-term batched GEMM
//   CTA tile 128x128, KC=32, 3-stage cp.async pipeline (prefetch distance 2)
// smem: sbody(512B) spun(512B) then 3 stages x {Ah,Ph,Pl} slabs of 8 KB
//   slab = 128 rows x 64B; swizzle phys_chunk16 = ch ^ ((row>>1)&3)
// ---------------------------------------------------------------------------
static constexpr int KC = 32;
static constexpr int OFF_SB  = 0;
static constexpr int OFF_SP  = 512;
static constexpr int OFF_BUF = 1024;
static constexpr int SLAB    = 8192;       // one 128x32 fp16 slab
static constexpr int STAGE   = 3 * SLAB;   // 24 KB
static constexpr int SMEM_TOTAL = OFF_BUF + 3 * STAGE;  // 74752 B -> occ 2

__device__ __forceinline__ void load_slab(uint32_t dst, const __half* __restrict__ g,
                                          int row0, int kk, int tid) {
    #pragma unroll
    for (int l = 0; l < 2; l++) {
        const int cidx = tid + l * 256;     // 0..511
        const int row  = cidx >> 2;
        const int ch   = cidx & 3;
        const uint32_t off = (uint32_t)(row * 64 + ((ch ^ ((row >> 1) & 3)) << 4));
        cp_async16(dst + off, g + (size_t)(row0 + row) * H_ + kk + ch * 8);
    }
}

__device__ __forceinline__ void load_stage(uint32_t buf, size_t base, int i0, int j0,
                                           int kk, int tid) {
    load_slab(buf,            g_Ah + base, i0, kk, tid);
    load_slab(buf + SLAB,     g_Ph + base, j0, kk, tid);
    load_slab(buf + 2 * SLAB, g_Pl + base, j0, kk, tid);
}

__global__ void __launch_bounds__(256, 2)
gemm_kernel(float* __restrict__ out) {
    extern __shared__ char smem[];
    const uint32_t sbase = smem_u32(smem);
    const int tid  = threadIdx.x;
    const int lane = tid & 31;
    const int warp = tid >> 5;
    const int m_base = (warp & 1) * 64;   // 2 warps over M
    const int n_base = (warp >> 1) * 32;  // 4 warps over N

    const int b  = blockIdx.z;
    const int i0 = blockIdx.y * 128;
    const int j0 = blockIdx.x * 128;
    const size_t base = (size_t)b * L_ * H_;

    // rank-1 vector slices
    if (tid < 128)       ((float*)(smem + OFF_SB))[tid]       = g_sbody[b * L_ + i0 + tid];
    else                 ((float*)(smem + OFF_SP))[tid - 128] = g_spun [b * L_ + j0 + (tid - 128)];

    float acc[4][4][4];
    #pragma unroll
    for (int mi = 0; mi < 4; mi++)
        #pragma unroll
        for (int ni = 0; ni < 4; ni++)
            #pragma unroll
            for (int k = 0; k < 4; k++) acc[mi][ni][k] = 0.f;

    // fragment addressing (constant per thread)
    const int a_row  = (lane & 7) + ((lane >> 3) & 1) * 8;
    const int a_half = lane >> 4;
    const int b_row  = (lane & 7) + (lane >> 4) * 8;
    const int b_half = (lane >> 3) & 1;

    // prologue: chunks 0 and 1
    load_stage(sbase + OFF_BUF,         base, i0, j0, 0,  tid); CP_COMMIT();
    load_stage(sbase + OFF_BUF + STAGE, base, i0, j0, KC, tid); CP_COMMIT();

    #pragma unroll
    for (int c = 0; c < 4; c++) {
        if (c < 3) CP_WAIT(1); else CP_WAIT(0);   // chunk c arrived
        __syncthreads();                          // + all warps done with buf[(c+2)%3]
        if (c + 2 < 4) {
            load_stage(sbase + OFF_BUF + ((c + 2) % 3) * STAGE, base, i0, j0,
                       (c + 2) * KC, tid);
            CP_COMMIT();
        }

        const uint32_t buf = sbase + OFF_BUF + (c % 3) * STAGE;
        #pragma unroll
        for (int ks = 0; ks < KC / 16; ks++) {
            // --- B fragments via ldmatrix.x4: 2 n-tiles per load ---
            uint32_t bH[4][2], bL[4][2];
            {
                const int chunk = ks * 2 + b_half;
                #pragma unroll
                for (int np = 0; np < 2; np++) {
                    const int nrow = n_base + np * 16 + b_row;
                    const uint32_t off = (uint32_t)(nrow * 64 + ((chunk ^ ((nrow >> 1) & 3)) << 4));
                    uint32_t r[4];
                    ldsm_x4(r, buf + SLAB + off);          // Ph
                    bH[np*2][0] = r[0]; bH[np*2][1] = r[1];
                    bH[np*2+1][0] = r[2]; bH[np*2+1][1] = r[3];
                    ldsm_x4(r, buf + 2 * SLAB + off);      // Pl
                    bL[np*2][0] = r[0]; bL[np*2][1] = r[1];
                    bL[np*2+1][0] = r[2]; bL[np*2+1][1] = r[3];
                }
            }
            // --- A fragments + MMAs (2 per mi,ni) ---
            const int achunk = ks * 2 + a_half;
            #pragma unroll
            for (int mi = 0; mi < 4; mi++) {
                uint32_t aH[4];
                const int arow = m_base + mi * 16 + a_row;
                const uint32_t off = (uint32_t)(arow * 64 + ((achunk ^ ((arow >> 1) & 3)) << 4));
                ldsm_x4(aH, buf + off);                    // Ah
                #pragma unroll
                for (int ni = 0; ni < 4; ni++) {
                    mma_f16(acc[mi][ni], aH, bH[ni]);      // ah*ph
                    mma_f16(acc[mi][ni], aH, bL[ni]);      // ah*pl
                }
            }
        }
    }

    // --- epilogue: acc + sbody[row] + spun[col] -> gmem (float2 stores) ---
    const float* sbV = (const float*)(smem + OFF_SB);
    const float* spV = (const float*)(smem + OFF_SP);
    const int r4 = lane >> 2;
    const int c2 = (lane & 3) << 1;
    float* outB = out + (size_t)b * L_ * L_;

    #pragma unroll
    for (int mi = 0; mi < 4; mi++) {
        const float sb0 = sbV[m_base + mi * 16 + r4];
        const float sb1 = sbV[m_base + mi * 16 + 8 + r4];
        const int row0 = i0 + m_base + mi * 16 + r4;
        #pragma unroll
        for (int ni = 0; ni < 4; ni++) {
            const int col = j0 + n_base + ni * 8 + c2;
            const float sp0 = spV[n_base + ni * 8 + c2];
            const float sp1 = spV[n_base + ni * 8 + c2 + 1];
            float2 v0 = make_float2(acc[mi][ni][0] + sb0 + sp0,
                                    acc[mi][ni][1] + sb0 + sp1);
            float2 v1 = make_float2(acc[mi][ni][2] + sb1 + sp0,
                                    acc[mi][ni][3] + sb1 + sp1);
            *reinterpret_cast<float2*>(outB + (size_t)row0 * L_ + col)       = v0;
            *reinterpret_cast<float2*>(outB + (size_t)(row0 + 8) * L_ + col) = v1;
        }
    }
}

// ---------------------------------------------------------------------------
// Launch
// ---------------------------------------------------------------------------
extern "C" void kernel_launch(void* const* d_in, const int* in_sizes, int n_in,
                              void* d_out, int out_size) {
    const float* body = (const float*)d_in[n_in - 3];
    const float* pun  = (const float*)d_in[n_in - 2];
    const float* w_u  = (const float*)d_in[n_in - 1];
    float* out = (float*)d_out;

    prep_kernel<<<(B_ * L_) / 8, 256>>>(body, pun, w_u);

    static bool attr_set = false;
    if (!attr_set) {
        cudaFuncSetAttribute(gemm_kernel, cudaFuncAttributeMaxDynamicSharedMemorySize, SMEM_TOTAL);
        attr_set = true;
    }
    gemm_kernel<<<dim3(8, 8, B_), 256, SMEM_TOTAL>>>(out);
}

// round 5
// speedup vs baseline: 1.6572x; 1.0714x over previous
#include <cuda_runtime.h>
#include <cuda_fp16.h>
#include <cstdint>

// Problem constants
#define B_  64
#define L_  1024
#define H_  128

// ---------------------------------------------------------------------------
// Scratch (allocation-free rule: __device__ globals)
// fp16 2-term scheme: a = body*w3 -> ah (fp16); p = pun -> ph + pl (fp16 pair)
// s_cross ≈ ah·ph + ah·pl   (dropped al·p ~ 2^-11 relative)
// ---------------------------------------------------------------------------
__device__ __align__(16) __half g_Ah[(size_t)B_*L_*H_];
__device__ __align__(16) __half g_Ph[(size_t)B_*L_*H_];
__device__ __align__(16) __half g_Pl[(size_t)B_*L_*H_];
__device__ float g_sbody[B_*L_];
__device__ float g_spun [B_*L_];

// ---------------------------------------------------------------------------
// Helpers (base-arch only: NO tcgen05 — ptxas target is sm_103, not sm_103a)
// ---------------------------------------------------------------------------
__device__ __forceinline__ uint32_t smem_u32(const void* p) {
    uint32_t a;
    asm("{ .reg .u64 t; cvta.to.shared.u64 t, %1; cvt.u32.u64 %0, t; }" : "=r"(a) : "l"(p));
    return a;
}

__device__ __forceinline__ void ldsm_x4(uint32_t* r, uint32_t addr) {
    asm volatile("ldmatrix.sync.aligned.m8n8.x4.shared.b16 {%0,%1,%2,%3}, [%4];"
        : "=r"(r[0]), "=r"(r[1]), "=r"(r[2]), "=r"(r[3]) : "r"(addr));
}

// D += A * B  (m16n8k16, fp16 in, f32 accum)
__device__ __forceinline__ void mma_f16(float* d, const uint32_t* a, const uint32_t* b) {
    asm volatile(
        "mma.sync.aligned.m16n8k16.row.col.f32.f16.f16.f32 "
        "{%0,%1,%2,%3}, {%4,%5,%6,%7}, {%8,%9}, {%0,%1,%2,%3};"
        : "+f"(d[0]), "+f"(d[1]), "+f"(d[2]), "+f"(d[3])
        : "r"(a[0]), "r"(a[1]), "r"(a[2]), "r"(a[3]), "r"(b[0]), "r"(b[1]));
}

__device__ __forceinline__ void cp_async16(uint32_t dst, const void* src) {
    asm volatile("cp.async.cg.shared.global [%0], [%1], 16;" :: "r"(dst), "l"(src));
}
#define CP_COMMIT() asm volatile("cp.async.commit_group;" ::: "memory")
#define CP_WAIT(n)  asm volatile("cp.async.wait_group %0;" :: "n"(n) : "memory")

// ---------------------------------------------------------------------------
// Kernel 1: preprocess — ah = fp16(body*w3); ph/pl = fp16 split of pun;
//           rank-1 dot products. One warp per row (float4 per lane).
// ---------------------------------------------------------------------------
__device__ __forceinline__ uint32_t pack_h2(float x, float y) {
    __half2 v(__float2half(x), __float2half(y));
    return *reinterpret_cast<uint32_t*>(&v);
}

__global__ void __launch_bounds__(256) prep_kernel(const float* __restrict__ body,
                                                   const float* __restrict__ pun,
                                                   const float* __restrict__ w_u) {
    const int warp = threadIdx.x >> 5, lane = threadIdx.x & 31;
    const int r = blockIdx.x * 8 + warp;
    const int d4 = lane * 4;

    const float4 w1 = *reinterpret_cast<const float4*>(w_u + d4);
    const float4 w2 = *reinterpret_cast<const float4*>(w_u + H_ + d4);
    const float4 w3 = *reinterpret_cast<const float4*>(w_u + 2 * H_ + d4);

    const size_t idx = (size_t)r * H_ + d4;
    const float4 bv = *reinterpret_cast<const float4*>(body + idx);
    const float4 pv = *reinterpret_cast<const float4*>(pun + idx);

    // A = body*w3 -> fp16 (single term)
    float a0 = bv.x * w3.x, a1 = bv.y * w3.y, a2 = bv.z * w3.z, a3 = bv.w * w3.w;
    *reinterpret_cast<uint2*>(g_Ah + idx) =
        make_uint2(pack_h2(a0, a1), pack_h2(a2, a3));

    // P = pun -> fp16 hi/lo split
    float q0 = __half2float(__float2half(pv.x));
    float q1 = __half2float(__float2half(pv.y));
    float q2 = __half2float(__float2half(pv.z));
    float q3 = __half2float(__float2half(pv.w));
    *reinterpret_cast<uint2*>(g_Ph + idx) =
        make_uint2(pack_h2(pv.x, pv.y), pack_h2(pv.z, pv.w));
    *reinterpret_cast<uint2*>(g_Pl + idx) =
        make_uint2(pack_h2(pv.x - q0, pv.y - q1), pack_h2(pv.z - q2, pv.w - q3));

    // rank-1 dot products
    float sb = bv.x * w1.x + bv.y * w1.y + bv.z * w1.z + bv.w * w1.w;
    float sp = pv.x * w2.x + pv.y * w2.y + pv.z * w2.z + pv.w * w2.w;
    #pragma unroll
    for (int o = 16; o > 0; o >>= 1) {
        sb += __shfl_down_sync(0xFFFFFFFFu, sb, o);
        sp += __shfl_down_sync(0xFFFFFFFFu, sp, o);
    }
    if (lane == 0) { g_sbody[r] = sb; g_spun[r] = sp; }
}

// ---------------------------------------------------------------------------
// Kernel 2: mma.sync fp16 2-term batched GEMM
//   CTA tile 128x128; WHOLE K=128 resident in smem (2 stages of KC=64).
//   Only 2 __syncthreads in the kernel; k-loops are barrier-free so ptxas
//   can software-pipeline LDSM/MMA across the full unroll.
// smem: sbody(512B) spun(512B) then 2 stages x {Ah,Ph,Pl} slabs of 16 KB
//   slab = 128 rows x 128B (64 fp16); swizzle phys_chunk16 = ch ^ (row&7)
// ---------------------------------------------------------------------------
static constexpr int KC = 64;
static constexpr int OFF_SB  = 0;
static constexpr int OFF_SP  = 512;
static constexpr int OFF_BUF = 1024;
static constexpr int SLAB    = 16384;      // one 128x64 fp16 slab
static constexpr int STAGE   = 3 * SLAB;   // 48 KB
static constexpr int SMEM_TOTAL = OFF_BUF + 2 * STAGE;  // 99328 B -> occ 2

__device__ __forceinline__ void load_slab(uint32_t dst, const __half* __restrict__ g,
                                          int row0, int kk, int tid) {
    #pragma unroll
    for (int l = 0; l < 4; l++) {
        const int cidx = tid + l * 256;     // 0..1023
        const int row  = cidx >> 3;
        const int ch   = cidx & 7;
        const uint32_t off = (uint32_t)(row * 128 + ((ch ^ (row & 7)) << 4));
        cp_async16(dst + off, g + (size_t)(row0 + row) * H_ + kk + ch * 8);
    }
}

__device__ __forceinline__ void load_stage(uint32_t buf, size_t base, int i0, int j0,
                                           int kk, int tid) {
    load_slab(buf,            g_Ah + base, i0, kk, tid);
    load_slab(buf + SLAB,     g_Ph + base, j0, kk, tid);
    load_slab(buf + 2 * SLAB, g_Pl + base, j0, kk, tid);
}

__global__ void __launch_bounds__(256, 2)
gemm_kernel(float* __restrict__ out) {
    extern __shared__ char smem[];
    const uint32_t sbase = smem_u32(smem);
    const int tid  = threadIdx.x;
    const int lane = tid & 31;
    const int warp = tid >> 5;
    const int m_base = (warp & 1) * 64;   // 2 warps over M
    const int n_base = (warp >> 1) * 32;  // 4 warps over N

    const int b  = blockIdx.z;
    const int i0 = blockIdx.y * 128;
    const int j0 = blockIdx.x * 128;
    const size_t base = (size_t)b * L_ * H_;

    // prologue: both K-chunks in flight immediately (max MLP)
    load_stage(sbase + OFF_BUF,         base, i0, j0, 0,  tid); CP_COMMIT();
    load_stage(sbase + OFF_BUF + STAGE, base, i0, j0, KC, tid); CP_COMMIT();

    // rank-1 vector slices (regular loads, overlap with cp.async)
    if (tid < 128)       ((float*)(smem + OFF_SB))[tid]       = g_sbody[b * L_ + i0 + tid];
    else                 ((float*)(smem + OFF_SP))[tid - 128] = g_spun [b * L_ + j0 + (tid - 128)];

    float acc[4][4][4];
    #pragma unroll
    for (int mi = 0; mi < 4; mi++)
        #pragma unroll
        for (int ni = 0; ni < 4; ni++)
            #pragma unroll
            for (int k = 0; k < 4; k++) acc[mi][ni][k] = 0.f;

    // fragment addressing (constant per thread)
    const int a_row  = (lane & 7) + ((lane >> 3) & 1) * 8;
    const int a_half = lane >> 4;
    const int b_row  = (lane & 7) + (lane >> 4) * 8;
    const int b_half = (lane >> 3) & 1;

    #pragma unroll
    for (int c = 0; c < 2; c++) {
        if (c == 0) CP_WAIT(1); else CP_WAIT(0);
        __syncthreads();   // all threads' copies for this stage visible

        const uint32_t buf = sbase + OFF_BUF + c * STAGE;
        #pragma unroll
        for (int ks = 0; ks < KC / 16; ks++) {
            // --- B fragments via ldmatrix.x4: 2 n-tiles per load ---
            uint32_t bH[4][2], bL[4][2];
            {
                const int chunk = ks * 2 + b_half;
                #pragma unroll
                for (int np = 0; np < 2; np++) {
                    const int nrow = n_base + np * 16 + b_row;
                    const uint32_t off = (uint32_t)(nrow * 128 + ((chunk ^ (nrow & 7)) << 4));
                    uint32_t r[4];
                    ldsm_x4(r, buf + SLAB + off);          // Ph
                    bH[np*2][0] = r[0]; bH[np*2][1] = r[1];
                    bH[np*2+1][0] = r[2]; bH[np*2+1][1] = r[3];
                    ldsm_x4(r, buf + 2 * SLAB + off);      // Pl
                    bL[np*2][0] = r[0]; bL[np*2][1] = r[1];
                    bL[np*2+1][0] = r[2]; bL[np*2+1][1] = r[3];
                }
            }
            // --- A fragments + MMAs (2 per mi,ni) ---
            const int achunk = ks * 2 + a_half;
            #pragma unroll
            for (int mi = 0; mi < 4; mi++) {
                uint32_t aH[4];
                const int arow = m_base + mi * 16 + a_row;
                const uint32_t off = (uint32_t)(arow * 128 + ((achunk ^ (arow & 7)) << 4));
                ldsm_x4(aH, buf + off);                    // Ah
                #pragma unroll
                for (int ni = 0; ni < 4; ni++) {
                    mma_f16(acc[mi][ni], aH, bH[ni]);      // ah*ph
                    mma_f16(acc[mi][ni], aH, bL[ni]);      // ah*pl
                }
            }
        }
    }

    // --- epilogue: acc + sbody[row] + spun[col] -> gmem, streaming stores ---
    const float* sbV = (const float*)(smem + OFF_SB);
    const float* spV = (const float*)(smem + OFF_SP);
    const int r4 = lane >> 2;
    const int c2 = (lane & 3) << 1;
    float* outB = out + (size_t)b * L_ * L_;

    #pragma unroll
    for (int mi = 0; mi < 4; mi++) {
        const float sb0 = sbV[m_base + mi * 16 + r4];
        const float sb1 = sbV[m_base + mi * 16 + 8 + r4];
        const int row0 = i0 + m_base + mi * 16 + r4;
        #pragma unroll
        for (int ni = 0; ni < 4; ni++) {
            const int col = j0 + n_base + ni * 8 + c2;
            const float sp0 = spV[n_base + ni * 8 + c2];
            const float sp1 = spV[n_base + ni * 8 + c2 + 1];
            float2 v0 = make_float2(acc[mi][ni][0] + sb0 + sp0,
                                    acc[mi][ni][1] + sb0 + sp1);
            float2 v1 = make_float2(acc[mi][ni][2] + sb1 + sp0,
                                    acc[mi][ni][3] + sb1 + sp1);
            __stcs(reinterpret_cast<float2*>(outB + (size_t)row0 * L_ + col), v0);
            __stcs(reinterpret_cast<float2*>(outB + (size_t)(row0 + 8) * L_ + col), v1);
        }
    }
}

// ---------------------------------------------------------------------------
// Launch
// ---------------------------------------------------------------------------
extern "C" void kernel_launch(void* const* d_in, const int* in_sizes, int n_in,
                              void* d_out, int out_size) {
    const float* body = (const float*)d_in[n_in - 3];
    const float* pun  = (const float*)d_in[n_in - 2];
    const float* w_u  = (const float*)d_in[n_in - 1];
    float* out = (float*)d_out;

    prep_kernel<<<(B_ * L_) / 8, 256>>>(body, pun, w_u);

    static bool attr_set = false;
    if (!attr_set) {
        cudaFuncSetAttribute(gemm_kernel, cudaFuncAttributeMaxDynamicSharedMemorySize, SMEM_TOTAL);
        attr_set = true;
    }
    gemm_kernel<<<dim3(8, 8, B_), 256, SMEM_TOTAL>>>(out);
}